// round 1
// baseline (speedup 1.0000x reference)
#include <cuda_runtime.h>
#include <math.h>

#define NROWS 4096
#define D     128
#define AWORD 16            // 512 label bits -> 16 u32 words
#define INV_TAU (1.0f/0.07f)

#define BM 32               // anchor rows per block
#define BI 128              // i-columns per tile
#define PITCH 129           // padded B pitch (floats) -> conflict-free LDS/STS
#define IBP 17              // padded ib pitch (u32)

// ---- scratch (static device memory; no allocations) ----
__device__ float    g_Z[2 * NROWS * D];       // normalized [z1n ; z2n]  (4 MB)
__device__ unsigned g_bits[NROWS * AWORD];    // packed labels
__device__ float    g_scnt[NROWS];            // per-row label count (as float)
__device__ float    g_rowloss[NROWS];

// ---------------- kernel 1: L2-normalize z1,z2 into g_Z ----------------
__global__ void knorm(const float* __restrict__ z1, const float* __restrict__ z2) {
    int r    = blockIdx.x * 8 + (threadIdx.x >> 5);   // one warp per row, 8192 rows
    int lane = threadIdx.x & 31;
    const float* src = (r < NROWS) ? (z1 + (size_t)r * D)
                                   : (z2 + (size_t)(r - NROWS) * D);
    float4 v = ((const float4*)src)[lane];
    float ss = v.x*v.x + v.y*v.y + v.z*v.z + v.w*v.w;
    #pragma unroll
    for (int o = 16; o; o >>= 1) ss += __shfl_xor_sync(0xffffffffu, ss, o);
    float nrm = sqrtf(ss);
    float inv = 1.0f / fmaxf(nrm, 1e-12f);
    float4 o4 = make_float4(v.x*inv, v.y*inv, v.z*inv, v.w*inv);
    ((float4*)(g_Z + (size_t)r * D))[lane] = o4;
}

// ---------------- kernel 2: pack labels into bitmasks + counts ----------------
__global__ void kpack(const int* __restrict__ labels) {
    int r    = blockIdx.x * 4 + (threadIdx.x >> 5);   // one warp per row
    int lane = threadIdx.x & 31;
    const int* lp = labels + (size_t)r * 512;
    int cnt = 0;
    unsigned myw = 0;
    #pragma unroll
    for (int w = 0; w < AWORD; ++w) {
        int v = lp[w * 32 + lane];
        unsigned word = __ballot_sync(0xffffffffu, v != 0);
        if (lane == w) myw = word;
        cnt += __popc(word);
    }
    if (lane < AWORD) g_bits[r * AWORD + lane] = myw;
    if (lane == 0)    g_scnt[r] = (float)cnt;
}

// ---------------- kernel 3: fused sim-GEMM + jaccard + softmax stats ----------------
__global__ void __launch_bounds__(256, 1) kmain() {
    extern __shared__ float sm[];
    float*    As = sm;                               // [BM][D]            4096 f
    float*    Bs = As + BM * D;                      // [2][BI][PITCH]    33024 f
    unsigned* jb = (unsigned*)(Bs + 2 * BI * PITCH); // [BM][AWORD]         512 u
    unsigned* ib = jb + BM * AWORD;                  // [BI][IBP]          2176 u
    float*    sj = (float*)(ib + BI * IBP);          // [BM]
    float*    si = sj + BM;                          // [BI]

    const int tid  = threadIdx.x;
    const int ry   = tid >> 5;        // warp id 0..7 -> 4 rows each
    const int ix   = tid & 31;        // lane -> i strided by 32
    const int row0 = blockIdx.x * BM;

    // A tile (persists whole kernel)
    for (int idx = tid; idx < BM * (D / 4); idx += 256) {
        int rr = idx >> 5, kk = idx & 31;
        ((float4*)As)[idx] = ((const float4*)(g_Z + (size_t)(row0 + rr) * D))[kk];
        (void)rr; (void)kk;
    }
    for (int idx = tid; idx < BM * AWORD; idx += 256)
        jb[idx] = g_bits[row0 * AWORD + idx];
    if (tid < BM) sj[tid] = g_scnt[row0 + tid];

    float r_sumexp[4] = {0,0,0,0};
    float r_possum[4] = {0,0,0,0};
    float r_npos[4]   = {0,0,0,0};

    for (int i0 = 0; i0 < NROWS; i0 += BI) {
        __syncthreads();   // protect Bs/ib vs previous iteration's readers (and A on iter 0)

        // B tile: both halves, [h][i][k] padded. Lanes consecutive in i -> conflict-free STS.
        for (int idx = tid; idx < 2 * BI * (D / 4); idx += 256) {
            int i  = idx & (BI - 1);
            int k4 = (idx >> 7) & 31;
            int h  = idx >> 12;
            float4 v = ((const float4*)(g_Z + (size_t)(h * NROWS + i0 + i) * D))[k4];
            float* dst = Bs + (h * BI + i) * PITCH + k4 * 4;
            dst[0] = v.x; dst[1] = v.y; dst[2] = v.z; dst[3] = v.w;
        }
        for (int idx = tid; idx < BI * AWORD; idx += 256) {
            int i = idx >> 4, w = idx & 15;
            ib[i * IBP + w] = g_bits[(i0 + i) * AWORD + w];
        }
        if (tid < BI) si[tid] = g_scnt[i0 + tid];
        __syncthreads();

        // ---- 4x4x2 register-blocked dot products over K=128 ----
        float acc[2][4][4];
        #pragma unroll
        for (int h = 0; h < 2; ++h)
            #pragma unroll
            for (int m = 0; m < 4; ++m)
                #pragma unroll
                for (int t = 0; t < 4; ++t) acc[h][m][t] = 0.0f;

        const float* A0 = As + (ry * 4) * D;
        const float* B0 = Bs + ix * PITCH;
        const float* B1 = B0 + BI * PITCH;

        #pragma unroll 4
        for (int k = 0; k < D; ++k) {
            float a[4];
            #pragma unroll
            for (int m = 0; m < 4; ++m) a[m] = A0[m * D + k];
            #pragma unroll
            for (int t = 0; t < 4; ++t) {
                float b1 = B0[t * 32 * PITCH + k];
                float b2 = B1[t * 32 * PITCH + k];
                #pragma unroll
                for (int m = 0; m < 4; ++m) {
                    acc[0][m][t] = fmaf(a[m], b1, acc[0][m][t]);
                    acc[1][m][t] = fmaf(a[m], b2, acc[1][m][t]);
                }
            }
        }

        // ---- per-pair post: exp, jaccard positivity, reductions ----
        #pragma unroll
        for (int t = 0; t < 4; ++t) {
            int ii = ix + 32 * t;
            int ig = i0 + ii;
            unsigned ibw[AWORD];
            #pragma unroll
            for (int w = 0; w < AWORD; ++w) ibw[w] = ib[ii * IBP + w];
            float s_i = si[ii];
            #pragma unroll
            for (int m = 0; m < 4; ++m) {
                int   j  = row0 + ry * 4 + m;
                float s1 = fmaf(acc[0][m][t], INV_TAU, -INV_TAU); // sim - m0
                float s2 = fmaf(acc[1][m][t], INV_TAU, -INV_TAU);
                float e1 = __expf(s1);
                float e2 = __expf(s2);
                int inter = 0;
                #pragma unroll
                for (int w = 0; w < AWORD; ++w)
                    inter += __popc(ibw[w] & jb[(ry * 4 + m) * AWORD + w]);
                // replicate reference exactly: inter / (union + 1e-8) with IEEE RN div
                float un  = sj[ry * 4 + m] + s_i - (float)inter + 1e-8f;
                bool  pos = (__fdiv_rn((float)inter, un) >= 0.3f);

                float se, ps, np;
                if (ig == j) { se = e2;       ps = s2;       np = 1.0f; } // col j excluded, col N+j forced pos
                else if (pos){ se = e1 + e2;  ps = s1 + s2;  np = 2.0f; }
                else         { se = e1 + e2;  ps = 0.0f;     np = 0.0f; }
                r_sumexp[m] += se;
                r_possum[m] += ps;
                r_npos[m]   += np;
            }
        }
    }

    // ---- per-row finish: each warp exclusively owns its 4 rows ----
    #pragma unroll
    for (int m = 0; m < 4; ++m) {
        float se = r_sumexp[m], ps = r_possum[m], np = r_npos[m];
        #pragma unroll
        for (int o = 16; o; o >>= 1) {
            se += __shfl_xor_sync(0xffffffffu, se, o);
            ps += __shfl_xor_sync(0xffffffffu, ps, o);
            np += __shfl_xor_sync(0xffffffffu, np, o);
        }
        if (ix == 0) {
            float lg = logf(se + 1e-8f);
            g_rowloss[row0 + ry * 4 + m] = -(ps - np * lg) / np;
        }
    }
}

// ---------------- kernel 4: final reduction ----------------
__global__ void kfinal(float* __restrict__ out) {
    __shared__ float red[256];
    float s = 0.0f;
    for (int i = threadIdx.x; i < NROWS; i += 256) s += g_rowloss[i];
    red[threadIdx.x] = s;
    __syncthreads();
    for (int o = 128; o; o >>= 1) {
        if (threadIdx.x < o) red[threadIdx.x] += red[threadIdx.x + o];
        __syncthreads();
    }
    if (threadIdx.x == 0) out[0] = red[0] / (float)NROWS;
}

// ---------------- launch ----------------
extern "C" void kernel_launch(void* const* d_in, const int* in_sizes, int n_in,
                              void* d_out, int out_size) {
    const float* z1     = (const float*)d_in[0];
    const float* z2     = (const float*)d_in[1];
    const int*   labels = (const int*)d_in[2];
    float* out = (float*)d_out;

    const int SMEM_BYTES = (BM * D + 2 * BI * PITCH) * 4
                         + (BM * AWORD + BI * IBP) * 4
                         + (BM + BI) * 4;   // 159,872 B
    cudaFuncSetAttribute(kmain, cudaFuncAttributeMaxDynamicSharedMemorySize, SMEM_BYTES);

    knorm<<<2 * NROWS / 8, 256>>>(z1, z2);
    kpack<<<NROWS / 4, 128>>>(labels);
    kmain<<<NROWS / BM, 256, SMEM_BYTES>>>();
    kfinal<<<1, 256>>>(out);
}

// round 3
// speedup vs baseline: 3.6230x; 3.6230x over previous
#include <cuda_runtime.h>
#include <cstdint>
#include <math.h>

#define NROWS 4096
#define D     128
#define AWORD 16
#define INV_TAU (1.0f/0.07f)
#define CT    4               // column tiles per block in kmain
#define PITCH 132             // smem tile pitch in floats (conflict-free)

// ---------------- static device scratch ----------------
__device__ float    g_Z[2 * NROWS * D];        // tf32-rounded normalized [z1n; z2n]
__device__ unsigned g_bits[NROWS * AWORD];     // packed labels
__device__ float    g_scnt[NROWS];             // label row sums
__device__ unsigned g_pm[NROWS * (NROWS/32)];  // pos_label bitmask [4096][128 words]
__device__ float    g_se[NROWS], g_ps[NROWS], g_np[NROWS];

// ---------------- helpers ----------------
__device__ __forceinline__ uint32_t smem_u32(const void* p) {
    uint32_t a;
    asm("{ .reg .u64 t; cvta.to.shared.u64 t, %1; cvt.u32.u64 %0, t; }" : "=r"(a) : "l"(p));
    return a;
}
__device__ __forceinline__ void cpa16(uint32_t dst, const void* src) {
    asm volatile("cp.async.cg.shared.global [%0], [%1], 16;" :: "r"(dst), "l"(src));
}
#define CP_COMMIT() asm volatile("cp.async.commit_group;" ::: "memory")
#define CP_WAIT0()  asm volatile("cp.async.wait_group 0;" ::: "memory")

__device__ __forceinline__ void mma_tf32(float* d, const uint32_t* a, const uint32_t* b) {
    asm volatile(
        "mma.sync.aligned.m16n8k8.row.col.f32.tf32.tf32.f32 "
        "{%0,%1,%2,%3}, {%4,%5,%6,%7}, {%8,%9}, {%0,%1,%2,%3};"
        : "+f"(d[0]), "+f"(d[1]), "+f"(d[2]), "+f"(d[3])
        : "r"(a[0]), "r"(a[1]), "r"(a[2]), "r"(a[3]), "r"(b[0]), "r"(b[1]));
}

// ---------------- kernel 1: L2-normalize + tf32 round ----------------
__global__ void knorm(const float* __restrict__ z1, const float* __restrict__ z2) {
    int r    = blockIdx.x * 8 + (threadIdx.x >> 5);
    int lane = threadIdx.x & 31;
    const float* src = (r < NROWS) ? (z1 + (size_t)r * D) : (z2 + (size_t)(r - NROWS) * D);
    float4 v = ((const float4*)src)[lane];
    float ss = v.x*v.x + v.y*v.y + v.z*v.z + v.w*v.w;
    #pragma unroll
    for (int o = 16; o; o >>= 1) ss += __shfl_xor_sync(0xffffffffu, ss, o);
    float inv = 1.0f / fmaxf(sqrtf(ss), 1e-12f);
    float o4[4] = {v.x*inv, v.y*inv, v.z*inv, v.w*inv};
    uint32_t t4[4];
    #pragma unroll
    for (int q = 0; q < 4; ++q)
        asm("cvt.rna.tf32.f32 %0, %1;" : "=r"(t4[q]) : "f"(o4[q]));
    ((uint4*)(g_Z + (size_t)r * D))[lane] = make_uint4(t4[0], t4[1], t4[2], t4[3]);
}

// ---------------- kernel 2: pack labels ----------------
__global__ void kpack(const int* __restrict__ labels) {
    int r    = blockIdx.x * 4 + (threadIdx.x >> 5);
    int lane = threadIdx.x & 31;
    const int* lp = labels + (size_t)r * 512;
    int cnt = 0; unsigned myw = 0;
    #pragma unroll
    for (int w = 0; w < AWORD; ++w) {
        unsigned word = __ballot_sync(0xffffffffu, lp[w * 32 + lane] != 0);
        if (lane == w) myw = word;
        cnt += __popc(word);
    }
    if (lane < AWORD) g_bits[r * AWORD + lane] = myw;
    if (lane == 0)    g_scnt[r] = (float)cnt;
}

// ---------------- kernel 2b: zero accumulators ----------------
__global__ void kzero() {
    int i = blockIdx.x * blockDim.x + threadIdx.x;
    if (i < NROWS) { g_se[i] = 0.f; g_ps[i] = 0.f; g_np[i] = 0.f; }
}

// ---------------- kernel 3: jaccard pos mask (upper triangle + ballot transpose) ----------------
__global__ void __launch_bounds__(128) kjacc() {
    int jb = blockIdx.y, ib = blockIdx.x;
    if (ib < jb) return;
    __shared__ uint4 sib4[128 * 4];
    __shared__ float ssi[128];

    int tid  = threadIdx.x;
    int lane = tid & 31, wid = tid >> 5;

    uint4 jr4[4];
    #pragma unroll
    for (int q = 0; q < 4; ++q)
        jr4[q] = ((const uint4*)(g_bits + (size_t)(jb*128 + tid) * AWORD))[q];
    float sjv = g_scnt[jb*128 + tid];
    #pragma unroll
    for (int q = 0; q < 4; ++q)
        sib4[q * 128 + tid] = ((const uint4*)(g_bits + (size_t)ib * 128 * AWORD))[q * 128 + tid];
    ssi[tid] = g_scnt[ib*128 + tid];
    __syncthreads();

    const unsigned* jr = (const unsigned*)jr4;
    unsigned myword = 0;
    unsigned tw[4];
    #pragma unroll 1
    for (int i = 0; i < 128; ++i) {
        const unsigned* iw = (const unsigned*)&sib4[i * 4];
        int inter = 0;
        #pragma unroll
        for (int w = 0; w < AWORD; ++w) inter += __popc(jr[w] & iw[w]);
        float fi  = (float)inter;
        float un  = sjv + ssi[i] - fi + 1e-8f;
        bool pos  = (__fdiv_rn(fi, un) >= 0.3f);
        myword |= (pos ? 1u : 0u) << (i & 31);
        unsigned bal = __ballot_sync(0xffffffffu, pos);
        if ((i & 31) == lane) tw[i >> 5] = bal;
        if ((i & 31) == 31) {
            g_pm[(size_t)(jb*128 + tid) * 128 + ib*4 + (i >> 5)] = myword;
            myword = 0;
        }
    }
    if (ib != jb) {
        #pragma unroll
        for (int q = 0; q < 4; ++q)
            g_pm[(size_t)(ib*128 + q*32 + lane) * 128 + jb*4 + wid] = tw[q];
    }
}

// ---------------- kernel 4: mma.sync tf32 sim GEMM + fused epilogue ----------------
// smem floats: As [0,16896), Bs0 [16896,33792), Bs1 [33792,50688), pm [50688,51712)
#define SM_A  0
#define SM_B0 16896
#define SM_B1 33792
#define SM_PM 50688
#define SMEM_FLOATS 51712

__global__ void __launch_bounds__(256, 1) kmain() {
    extern __shared__ float sm[];
    const int tid  = threadIdx.x;
    const int lane = tid & 31, wid = tid >> 5;
    const int wm   = wid >> 1, wn = wid & 1;      // 4 m-warps x 2 n-warps
    const int g    = lane >> 2, tg = lane & 3;
    const int jb   = blockIdx.y;
    const int ct0  = blockIdx.x * CT;

    uint32_t sb = smem_u32(sm);

    // ---- prologue: A tile + B tile 0 + pm words 0 ----
    {
        const float* Asrc = g_Z + (size_t)jb  * 128 * D;
        const float* Bsrc = g_Z + (size_t)ct0 * 128 * D;
        #pragma unroll
        for (int it = 0; it < 16; ++it) {
            int idx = it * 256 + tid;
            int r = idx >> 5, k4 = idx & 31;
            uint32_t off = (uint32_t)(r * PITCH + k4 * 4) * 4u;
            cpa16(sb + off,               Asrc + r * 128 + k4 * 4);
            cpa16(sb + SM_B0 * 4u + off,  Bsrc + r * 128 + k4 * 4);
        }
        if (tid < 128)
            cpa16(sb + SM_PM * 4u + tid * 16,
                  g_pm + (size_t)(jb * 128 + tid) * 128 + ((ct0 & 31) << 2));
        CP_COMMIT();
        CP_WAIT0();
    }
    __syncthreads();

    float se[4] = {0,0,0,0}, ps[4] = {0,0,0,0}, np[4] = {0,0,0,0};

    for (int t = 0; t < CT; ++t) {
        const int ctile = ct0 + t;
        const float*    Bs  = sm + ((t & 1) ? SM_B1 : SM_B0);
        const unsigned* pmS = (const unsigned*)(sm + SM_PM) + (t & 1) * 512;

        // prefetch next B tile + pm into the other buffers
        if (t + 1 < CT) {
            const float* Bsrc = g_Z + (size_t)(ctile + 1) * 128 * D;
            uint32_t bo = sb + (((t + 1) & 1) ? SM_B1 : SM_B0) * 4u;
            #pragma unroll
            for (int it = 0; it < 16; ++it) {
                int idx = it * 256 + tid;
                int r = idx >> 5, k4 = idx & 31;
                cpa16(bo + (uint32_t)(r * PITCH + k4 * 4) * 4u, Bsrc + r * 128 + k4 * 4);
            }
            if (tid < 128)
                cpa16(sb + (SM_PM + ((t + 1) & 1) * 512) * 4u + tid * 16,
                      g_pm + (size_t)(jb * 128 + tid) * 128 + (((ctile + 1) & 31) << 2));
            CP_COMMIT();
        }

        // ---- 32x64 warp tile: 2 m-frags x 8 n-frags, K=128 in 16 steps ----
        float d[2][8][4];
        #pragma unroll
        for (int mf = 0; mf < 2; ++mf)
            #pragma unroll
            for (int nf = 0; nf < 8; ++nf)
                #pragma unroll
                for (int q = 0; q < 4; ++q) d[mf][nf][q] = 0.0f;

        const float* Aw = sm + SM_A + (wm * 32) * PITCH;
        const float* Bw = Bs + (wn * 64) * PITCH;

        #pragma unroll 4
        for (int ks = 0; ks < 16; ++ks) {
            const int k0 = ks * 8;
            uint32_t a[2][4];
            #pragma unroll
            for (int mf = 0; mf < 2; ++mf) {
                const float* Ar = Aw + (mf * 16 + g) * PITCH + k0 + tg;
                a[mf][0] = __float_as_uint(Ar[0]);
                a[mf][1] = __float_as_uint(Ar[8 * PITCH]);
                a[mf][2] = __float_as_uint(Ar[4]);
                a[mf][3] = __float_as_uint(Ar[8 * PITCH + 4]);
            }
            #pragma unroll
            for (int nf = 0; nf < 8; ++nf) {
                const float* Br = Bw + (nf * 8 + g) * PITCH + k0 + tg;
                uint32_t b[2] = { __float_as_uint(Br[0]), __float_as_uint(Br[4]) };
                mma_tf32(d[0][nf], a[0], b);
                mma_tf32(d[1][nf], a[1], b);
            }
        }

        // ---- fused epilogue ----
        const int c0 = ctile * 128;
        #pragma unroll
        for (int mf = 0; mf < 2; ++mf) {
            #pragma unroll
            for (int h = 0; h < 2; ++h) {
                const int rl   = wm * 32 + mf * 16 + h * 8 + g;
                const int jr   = jb * 128 + rl;
                const int jaug = jr + NROWS;
                const int ai   = mf * 2 + h;
                float a_se = 0.f, a_ps = 0.f, a_np = 0.f;
                #pragma unroll
                for (int nf = 0; nf < 8; ++nf) {
                    const int cl = wn * 64 + nf * 8 + tg * 2;
                    const unsigned w = pmS[rl * 4 + (cl >> 5)];
                    #pragma unroll
                    for (int q = 0; q < 2; ++q) {
                        const int cg = c0 + cl + q;
                        float v = d[mf][nf][h * 2 + q];
                        float s = fmaf(v, INV_TAU, -INV_TAU);
                        float e = __expf(s);
                        bool pos = (((w >> ((cl + q) & 31)) & 1u) != 0u) | (cg == jaug);
                        if (cg != jr) {
                            a_se += e;
                            if (pos) { a_ps += s; a_np += 1.f; }
                        }
                    }
                }
                se[ai] += a_se; ps[ai] += a_ps; np[ai] += a_np;
            }
        }

        if (t + 1 < CT) CP_WAIT0();
        __syncthreads();
    }

    // ---- per-row reduce over the 4 lanes sharing a row, then atomic merge ----
    #pragma unroll
    for (int ai = 0; ai < 4; ++ai) {
        float a = se[ai], b = ps[ai], c = np[ai];
        a += __shfl_xor_sync(0xffffffffu, a, 1); a += __shfl_xor_sync(0xffffffffu, a, 2);
        b += __shfl_xor_sync(0xffffffffu, b, 1); b += __shfl_xor_sync(0xffffffffu, b, 2);
        c += __shfl_xor_sync(0xffffffffu, c, 1); c += __shfl_xor_sync(0xffffffffu, c, 2);
        if (tg == 0) {
            int row = jb * 128 + wm * 32 + (ai >> 1) * 16 + (ai & 1) * 8 + g;
            atomicAdd(&g_se[row], a);
            atomicAdd(&g_ps[row], b);
            atomicAdd(&g_np[row], c);
        }
    }
}

// ---------------- kernel 5: per-row loss + mean ----------------
__global__ void kfinal(float* __restrict__ out) {
    __shared__ float red[1024];
    int tid = threadIdx.x;
    float s = 0.0f;
    for (int i = tid; i < NROWS; i += 1024) {
        float npv = g_np[i];                 // >= 1 (aug column)
        s += -(g_ps[i] - npv * logf(g_se[i] + 1e-8f)) / npv;
    }
    red[tid] = s;
    __syncthreads();
    for (int o = 512; o; o >>= 1) {
        if (tid < o) red[tid] += red[tid + o];
        __syncthreads();
    }
    if (tid == 0) out[0] = red[0] / (float)NROWS;
}

// ---------------- launch ----------------
extern "C" void kernel_launch(void* const* d_in, const int* in_sizes, int n_in,
                              void* d_out, int out_size) {
    const float* z1     = (const float*)d_in[0];
    const float* z2     = (const float*)d_in[1];
    const int*   labels = (const int*)d_in[2];
    float* out = (float*)d_out;

    cudaFuncSetAttribute(kmain, cudaFuncAttributeMaxDynamicSharedMemorySize,
                         SMEM_FLOATS * 4);

    knorm<<<2 * NROWS / 8, 256>>>(z1, z2);
    kpack<<<NROWS / 4, 128>>>(labels);
    kzero<<<(NROWS + 255) / 256, 256>>>();
    kjacc<<<dim3(32, 32), 128>>>();
    kmain<<<dim3((2 * NROWS / 128) / CT, NROWS / 128), 256, SMEM_FLOATS * 4>>>();
    kfinal<<<1, 1024>>>(out);
}

// round 4
// speedup vs baseline: 4.4059x; 1.2161x over previous
#include <cuda_runtime.h>
#include <cstdint>
#include <math.h>

#define NROWS 4096
#define D     128
#define AWORD 16
#define INV_TAU (1.0f/0.07f)
#define PITCH 132             // smem tile pitch in floats (conflict-free)
#define CHUNK 14              // tiles per block in kmain (2048 tiles / 147 blocks)
#define NBLK  147

// ---------------- static device scratch ----------------
__device__ float    g_Z[2 * NROWS * D];        // tf32-rounded normalized [z1n; z2n]
__device__ unsigned g_bits[NROWS * AWORD];     // packed labels
__device__ int      g_cnt[NROWS];              // label row sums (int)
__device__ unsigned g_pm[NROWS * (NROWS/32)];  // pos_label bitmask [4096][128 words]
__device__ float    g_se[NROWS], g_ps[NROWS], g_np[NROWS];

// ---------------- helpers ----------------
__device__ __forceinline__ uint32_t smem_u32(const void* p) {
    uint32_t a;
    asm("{ .reg .u64 t; cvta.to.shared.u64 t, %1; cvt.u32.u64 %0, t; }" : "=r"(a) : "l"(p));
    return a;
}
__device__ __forceinline__ void cpa16(uint32_t dst, const void* src) {
    asm volatile("cp.async.cg.shared.global [%0], [%1], 16;" :: "r"(dst), "l"(src));
}
#define CP_COMMIT() asm volatile("cp.async.commit_group;" ::: "memory")
#define CP_WAIT0()  asm volatile("cp.async.wait_group 0;" ::: "memory")

__device__ __forceinline__ void mma_tf32(float* d, const uint32_t* a, const uint32_t* b) {
    asm volatile(
        "mma.sync.aligned.m16n8k8.row.col.f32.tf32.tf32.f32 "
        "{%0,%1,%2,%3}, {%4,%5,%6,%7}, {%8,%9}, {%0,%1,%2,%3};"
        : "+f"(d[0]), "+f"(d[1]), "+f"(d[2]), "+f"(d[3])
        : "r"(a[0]), "r"(a[1]), "r"(a[2]), "r"(a[3]), "r"(b[0]), "r"(b[1]));
}

// ---------------- kernel 1: L2-normalize + tf32 round ----------------
__global__ void knorm(const float* __restrict__ z1, const float* __restrict__ z2) {
    int r    = blockIdx.x * 8 + (threadIdx.x >> 5);
    int lane = threadIdx.x & 31;
    const float* src = (r < NROWS) ? (z1 + (size_t)r * D) : (z2 + (size_t)(r - NROWS) * D);
    float4 v = ((const float4*)src)[lane];
    float ss = v.x*v.x + v.y*v.y + v.z*v.z + v.w*v.w;
    #pragma unroll
    for (int o = 16; o; o >>= 1) ss += __shfl_xor_sync(0xffffffffu, ss, o);
    float inv = 1.0f / fmaxf(sqrtf(ss), 1e-12f);
    float o4[4] = {v.x*inv, v.y*inv, v.z*inv, v.w*inv};
    uint32_t t4[4];
    #pragma unroll
    for (int q = 0; q < 4; ++q)
        asm("cvt.rna.tf32.f32 %0, %1;" : "=r"(t4[q]) : "f"(o4[q]));
    ((uint4*)(g_Z + (size_t)r * D))[lane] = make_uint4(t4[0], t4[1], t4[2], t4[3]);
}

// ---------------- kernel 2: pack labels + zero accumulators ----------------
__global__ void kpack(const int* __restrict__ labels) {
    int tid  = threadIdx.x;
    int r    = blockIdx.x * 4 + (tid >> 5);
    int lane = tid & 31;
    int gidx = blockIdx.x * 128 + tid;
    if (gidx < NROWS) { g_se[gidx] = 0.f; g_ps[gidx] = 0.f; g_np[gidx] = 0.f; }
    const int* lp = labels + (size_t)r * 512;
    int cnt = 0; unsigned myw = 0;
    #pragma unroll
    for (int w = 0; w < AWORD; ++w) {
        unsigned word = __ballot_sync(0xffffffffu, lp[w * 32 + lane] != 0);
        if (lane == w) myw = word;
        cnt += __popc(word);
    }
    if (lane < AWORD) g_bits[r * AWORD + lane] = myw;
    if (lane == 0)    g_cnt[r] = cnt;
}

// ---------------- kernel 3: jaccard pos mask — integer test, triangular grid ----------------
// pos <=> __fdiv_rn(inter, union) >= 0.3f  <=>  inter>0 && (inter<<26) >= 20132659*union
// (exact: union,inter integers <= 1024; +1e-8f rounds away; tie impossible, 20132659 odd)
__global__ void __launch_bounds__(128) kjacc() {
    // triangular decode: 528 blocks -> (jb, ib) with jb <= ib < 32
    int rem = blockIdx.x, jb = 0;
    while (rem >= 32 - jb) { rem -= 32 - jb; ++jb; }
    int ib = jb + rem;

    __shared__ unsigned sib[128 * AWORD];
    __shared__ int      sci[128];

    int tid  = threadIdx.x;
    int lane = tid & 31, wid = tid >> 5;

    uint4 jr4[4];
    #pragma unroll
    for (int q = 0; q < 4; ++q)
        jr4[q] = ((const uint4*)(g_bits + (size_t)(jb*128 + tid) * AWORD))[q];
    const unsigned* jr = (const unsigned*)jr4;
    int sj = g_cnt[jb*128 + tid];
    #pragma unroll
    for (int q = 0; q < 4; ++q)
        ((uint4*)sib)[q * 128 + tid] = ((const uint4*)(g_bits + (size_t)ib * 128 * AWORD))[q * 128 + tid];
    sci[tid] = g_cnt[ib*128 + tid];
    __syncthreads();

    unsigned myword = 0;
    unsigned tw[4];
    #pragma unroll 2
    for (int i0 = 0; i0 < 128; i0 += 2) {
        const unsigned* iwA = sib + i0 * AWORD;
        const unsigned* iwB = iwA + AWORD;
        int a0=0, a1=0, a2=0, a3=0, b0=0, b1=0, b2=0, b3=0;
        #pragma unroll
        for (int w = 0; w < 4; ++w) {
            a0 += __popc(jr[w]      & iwA[w]);
            a1 += __popc(jr[w + 4]  & iwA[w + 4]);
            a2 += __popc(jr[w + 8]  & iwA[w + 8]);
            a3 += __popc(jr[w + 12] & iwA[w + 12]);
            b0 += __popc(jr[w]      & iwB[w]);
            b1 += __popc(jr[w + 4]  & iwB[w + 4]);
            b2 += __popc(jr[w + 8]  & iwB[w + 8]);
            b3 += __popc(jr[w + 12] & iwB[w + 12]);
        }
        int iA = (a0 + a1) + (a2 + a3);
        int iB = (b0 + b1) + (b2 + b3);
        long long uA = (long long)(sj + sci[i0]     - iA);
        long long uB = (long long)(sj + sci[i0 + 1] - iB);
        bool posA = (iA > 0) && (((long long)iA << 26) >= 20132659LL * uA);
        bool posB = (iB > 0) && (((long long)iB << 26) >= 20132659LL * uB);
        myword |= (posA ? 1u : 0u) << (i0 & 31);
        myword |= (posB ? 1u : 0u) << ((i0 + 1) & 31);
        unsigned balA = __ballot_sync(0xffffffffu, posA);
        unsigned balB = __ballot_sync(0xffffffffu, posB);
        if ((i0 & 31) == lane)       tw[i0 >> 5] = balA;
        if (((i0 + 1) & 31) == lane) tw[i0 >> 5] = balB;
        if ((i0 & 31) == 30) {
            g_pm[(size_t)(jb*128 + tid) * 128 + ib*4 + (i0 >> 5)] = myword;
            myword = 0;
        }
    }
    if (ib != jb) {
        #pragma unroll
        for (int q = 0; q < 4; ++q)
            g_pm[(size_t)(ib*128 + q*32 + lane) * 128 + jb*4 + wid] = tw[q];
    }
}

// ---------------- kernel 4: persistent mma.sync tf32 GEMM + fused epilogue ----------------
// smem floats: As [0,16896), Bs0 [16896,33792), Bs1 [33792,50688), pm [50688,51712)
#define SM_A  0
#define SM_B0 16896
#define SM_B1 33792
#define SM_PM 50688
#define SMEM_FLOATS 51712

__device__ __forceinline__ void ld_tileA(uint32_t sb, int jb, int tid) {
    const float* Asrc = g_Z + (size_t)jb * 128 * D;
    #pragma unroll
    for (int it = 0; it < 16; ++it) {
        int idx = it * 256 + tid;
        int r = idx >> 5, k4 = idx & 31;
        cpa16(sb + (uint32_t)(r * PITCH + k4 * 4) * 4u, Asrc + r * 128 + k4 * 4);
    }
}
__device__ __forceinline__ void ld_tileB(uint32_t sb, int t, int jb, int tid) {
    const float* Bsrc = g_Z + (size_t)(t & 63) * 128 * D;
    uint32_t bo = sb + ((t & 1) ? SM_B1 : SM_B0) * 4u;
    #pragma unroll
    for (int it = 0; it < 16; ++it) {
        int idx = it * 256 + tid;
        int r = idx >> 5, k4 = idx & 31;
        cpa16(bo + (uint32_t)(r * PITCH + k4 * 4) * 4u, Bsrc + r * 128 + k4 * 4);
    }
    if (tid < 128)
        cpa16(sb + (SM_PM + (t & 1) * 512) * 4u + tid * 16,
              g_pm + (size_t)(jb * 128 + tid) * 128 + (((t & 63) & 31) << 2));
}

__global__ void __launch_bounds__(256, 1) kmain() {
    extern __shared__ float sm[];
    const int tid  = threadIdx.x;
    const int lane = tid & 31, wid = tid >> 5;
    const int wm   = wid >> 1, wn = wid & 1;      // 4 m-warps x 2 n-warps
    const int g    = lane >> 2, tg = lane & 3;

    const int t0 = blockIdx.x * CHUNK;
    const int t1 = min(t0 + CHUNK, 2048);
    if (t0 >= 2048) return;

    uint32_t sb = smem_u32(sm);

    float se[4] = {0,0,0,0}, ps[4] = {0,0,0,0}, np[4] = {0,0,0,0};
    int jb = t0 >> 6;

    ld_tileA(sb, jb, tid);
    ld_tileB(sb, t0, jb, tid);
    CP_COMMIT(); CP_WAIT0();
    __syncthreads();

    for (int t = t0; t < t1; ++t) {
        const int  ct   = t & 63;
        const bool same = (t + 1 < t1) && (((t + 1) >> 6) == jb);
        if (same) { ld_tileB(sb, t + 1, jb, tid); CP_COMMIT(); }

        const float*    Bs  = sm + ((t & 1) ? SM_B1 : SM_B0);
        const unsigned* pmS = (const unsigned*)(sm + SM_PM) + (t & 1) * 512;

        // ---- 32x64 warp tile: 2 m-frags x 8 n-frags, K=128 in 16 steps ----
        float d[2][8][4];
        #pragma unroll
        for (int mf = 0; mf < 2; ++mf)
            #pragma unroll
            for (int nf = 0; nf < 8; ++nf)
                #pragma unroll
                for (int q = 0; q < 4; ++q) d[mf][nf][q] = 0.0f;

        const float* Aw = sm + SM_A + (wm * 32) * PITCH;
        const float* Bw = Bs + (wn * 64) * PITCH;

        #pragma unroll 4
        for (int ks = 0; ks < 16; ++ks) {
            const int k0 = ks * 8;
            uint32_t a[2][4];
            #pragma unroll
            for (int mf = 0; mf < 2; ++mf) {
                const float* Ar = Aw + (mf * 16 + g) * PITCH + k0 + tg;
                a[mf][0] = __float_as_uint(Ar[0]);
                a[mf][1] = __float_as_uint(Ar[8 * PITCH]);
                a[mf][2] = __float_as_uint(Ar[4]);
                a[mf][3] = __float_as_uint(Ar[8 * PITCH + 4]);
            }
            #pragma unroll
            for (int nf = 0; nf < 8; ++nf) {
                const float* Br = Bw + (nf * 8 + g) * PITCH + k0 + tg;
                uint32_t b[2] = { __float_as_uint(Br[0]), __float_as_uint(Br[4]) };
                mma_tf32(d[0][nf], a[0], b);
                mma_tf32(d[1][nf], a[1], b);
            }
        }

        // ---- fused epilogue ----
        const int c0 = ct * 128;
        #pragma unroll
        for (int mf = 0; mf < 2; ++mf) {
            #pragma unroll
            for (int h = 0; h < 2; ++h) {
                const int rl   = wm * 32 + mf * 16 + h * 8 + g;
                const int jr   = jb * 128 + rl;
                const int jaug = jr + NROWS;
                const int ai   = mf * 2 + h;
                float a_se = 0.f, a_ps = 0.f, a_np = 0.f;
                #pragma unroll
                for (int nf = 0; nf < 8; ++nf) {
                    const int cl = wn * 64 + nf * 8 + tg * 2;
                    const unsigned w = pmS[rl * 4 + (cl >> 5)];
                    #pragma unroll
                    for (int q = 0; q < 2; ++q) {
                        const int cg = c0 + cl + q;
                        float v = d[mf][nf][h * 2 + q];
                        float s = fmaf(v, INV_TAU, -INV_TAU);
                        float e = __expf(s);
                        bool pos = (((w >> ((cl + q) & 31)) & 1u) != 0u) | (cg == jaug);
                        if (cg != jr) {
                            a_se += e;
                            if (pos) { a_ps += s; a_np += 1.f; }
                        }
                    }
                }
                se[ai] += a_se; ps[ai] += a_ps; np[ai] += a_np;
            }
        }

        if (same) CP_WAIT0();
        __syncthreads();

        if (!same) {
            // flush accumulators for this jb
            #pragma unroll
            for (int ai = 0; ai < 4; ++ai) {
                float a = se[ai], b = ps[ai], c = np[ai];
                a += __shfl_xor_sync(0xffffffffu, a, 1); a += __shfl_xor_sync(0xffffffffu, a, 2);
                b += __shfl_xor_sync(0xffffffffu, b, 1); b += __shfl_xor_sync(0xffffffffu, b, 2);
                c += __shfl_xor_sync(0xffffffffu, c, 1); c += __shfl_xor_sync(0xffffffffu, c, 2);
                if (tg == 0) {
                    int row = jb * 128 + wm * 32 + (ai >> 1) * 16 + (ai & 1) * 8 + g;
                    atomicAdd(&g_se[row], a);
                    atomicAdd(&g_ps[row], b);
                    atomicAdd(&g_np[row], c);
                }
                se[ai] = 0.f; ps[ai] = 0.f; np[ai] = 0.f;
            }
            if (t + 1 < t1) {
                jb = (t + 1) >> 6;
                ld_tileA(sb, jb, tid);
                ld_tileB(sb, t + 1, jb, tid);
                CP_COMMIT(); CP_WAIT0();
                __syncthreads();
            }
        }
    }
}

// ---------------- kernel 5: per-row loss + mean ----------------
__global__ void kfinal(float* __restrict__ out) {
    __shared__ float red[1024];
    int tid = threadIdx.x;
    float s = 0.0f;
    for (int i = tid; i < NROWS; i += 1024) {
        float npv = g_np[i];                 // >= 1 (aug column)
        s += -(g_ps[i] - npv * logf(g_se[i] + 1e-8f)) / npv;
    }
    red[tid] = s;
    __syncthreads();
    for (int o = 512; o; o >>= 1) {
        if (tid < o) red[tid] += red[tid + o];
        __syncthreads();
    }
    if (tid == 0) out[0] = red[0] / (float)NROWS;
}

// ---------------- launch ----------------
extern "C" void kernel_launch(void* const* d_in, const int* in_sizes, int n_in,
                              void* d_out, int out_size) {
    const float* z1     = (const float*)d_in[0];
    const float* z2     = (const float*)d_in[1];
    const int*   labels = (const int*)d_in[2];
    float* out = (float*)d_out;

    cudaFuncSetAttribute(kmain, cudaFuncAttributeMaxDynamicSharedMemorySize,
                         SMEM_FLOATS * 4);

    knorm<<<2 * NROWS / 8, 256>>>(z1, z2);
    kpack<<<NROWS / 4, 128>>>(labels);
    kjacc<<<528, 128>>>();
    kmain<<<NBLK, 256, SMEM_FLOATS * 4>>>();
    kfinal<<<1, 1024>>>(out);
}

// round 5
// speedup vs baseline: 4.5516x; 1.0331x over previous
#include <cuda_runtime.h>
#include <cstdint>
#include <math.h>

#define NROWS 4096
#define D     128
#define AWORD 16
#define INV_TAU (1.0f/0.07f)
#define PITCH 132             // smem tile pitch in floats (conflict-free)
#define CHUNK 14              // tiles per block in kmain (2048 tiles / 147 blocks)
#define NBLK  147

// ---------------- static device scratch ----------------
__device__ float    g_Z[2 * NROWS * D];        // tf32-rounded normalized [z1n; z2n]
__device__ unsigned g_bits[NROWS * AWORD];     // packed labels
__device__ int      g_cnt[NROWS];              // label row sums (int)
__device__ unsigned g_pm[NROWS * (NROWS/32)];  // pos_label bitmask [4096][128 words]
__device__ float    g_se[NROWS], g_ps[NROWS], g_np[NROWS];

// ---------------- helpers ----------------
__device__ __forceinline__ uint32_t smem_u32(const void* p) {
    uint32_t a;
    asm("{ .reg .u64 t; cvta.to.shared.u64 t, %1; cvt.u32.u64 %0, t; }" : "=r"(a) : "l"(p));
    return a;
}
__device__ __forceinline__ void cpa16(uint32_t dst, const void* src) {
    asm volatile("cp.async.cg.shared.global [%0], [%1], 16;" :: "r"(dst), "l"(src));
}
#define CP_COMMIT() asm volatile("cp.async.commit_group;" ::: "memory")
#define CP_WAIT0()  asm volatile("cp.async.wait_group 0;" ::: "memory")

__device__ __forceinline__ void mma_tf32(float* d, const uint32_t* a, const uint32_t* b) {
    asm volatile(
        "mma.sync.aligned.m16n8k8.row.col.f32.tf32.tf32.f32 "
        "{%0,%1,%2,%3}, {%4,%5,%6,%7}, {%8,%9}, {%0,%1,%2,%3};"
        : "+f"(d[0]), "+f"(d[1]), "+f"(d[2]), "+f"(d[3])
        : "r"(a[0]), "r"(a[1]), "r"(a[2]), "r"(a[3]), "r"(b[0]), "r"(b[1]));
}

// ---------------- kernel 1: fused prep — L2-normalize+tf32 round / pack+zero ----------------
__global__ void kprep(const float* __restrict__ z1, const float* __restrict__ z2,
                      const int* __restrict__ labels) {
    const int tid  = threadIdx.x;
    const int wid  = tid >> 5;
    const int lane = tid & 31;

    if (blockIdx.x < 1024) {
        // --- normalize: 8 rows per block ---
        int r = blockIdx.x * 8 + wid;
        const float* src = (r < NROWS) ? (z1 + (size_t)r * D) : (z2 + (size_t)(r - NROWS) * D);
        float4 v = ((const float4*)src)[lane];
        float ss = v.x*v.x + v.y*v.y + v.z*v.z + v.w*v.w;
        #pragma unroll
        for (int o = 16; o; o >>= 1) ss += __shfl_xor_sync(0xffffffffu, ss, o);
        float inv = 1.0f / fmaxf(sqrtf(ss), 1e-12f);
        float o4[4] = {v.x*inv, v.y*inv, v.z*inv, v.w*inv};
        uint32_t t4[4];
        #pragma unroll
        for (int q = 0; q < 4; ++q)
            asm("cvt.rna.tf32.f32 %0, %1;" : "=r"(t4[q]) : "f"(o4[q]));
        ((uint4*)(g_Z + (size_t)r * D))[lane] = make_uint4(t4[0], t4[1], t4[2], t4[3]);
    } else {
        // --- pack labels: 8 rows per block, + zero accumulators ---
        int b2 = blockIdx.x - 1024;                 // 0..511
        int r  = b2 * 8 + wid;
        int gidx = b2 * 256 + tid;
        if (gidx < NROWS) { g_se[gidx] = 0.f; g_ps[gidx] = 0.f; g_np[gidx] = 0.f; }
        const int* lp = labels + (size_t)r * 512;
        int cnt = 0; unsigned myw = 0;
        #pragma unroll
        for (int w = 0; w < AWORD; ++w) {
            unsigned word = __ballot_sync(0xffffffffu, lp[w * 32 + lane] != 0);
            if (lane == w) myw = word;
            cnt += __popc(word);
        }
        if (lane < AWORD) g_bits[r * AWORD + lane] = myw;
        if (lane == 0)    g_cnt[r] = cnt;
    }
}

// ---------------- kernel 2: jaccard pos mask — integer test, triangular grid ----------------
// pos <=> __fdiv_rn(inter, union) >= 0.3f  <=>  inter>0 && (inter<<26) >= 20132659*union
__global__ void __launch_bounds__(128) kjacc() {
    int rem = blockIdx.x, jb = 0;
    while (rem >= 32 - jb) { rem -= 32 - jb; ++jb; }
    int ib = jb + rem;

    __shared__ unsigned sib[128 * AWORD];
    __shared__ int      sci[128];

    int tid  = threadIdx.x;
    int lane = tid & 31, wid = tid >> 5;

    uint4 jr4[4];
    #pragma unroll
    for (int q = 0; q < 4; ++q)
        jr4[q] = ((const uint4*)(g_bits + (size_t)(jb*128 + tid) * AWORD))[q];
    const unsigned* jr = (const unsigned*)jr4;
    int sj = g_cnt[jb*128 + tid];
    #pragma unroll
    for (int q = 0; q < 4; ++q)
        ((uint4*)sib)[q * 128 + tid] = ((const uint4*)(g_bits + (size_t)ib * 128 * AWORD))[q * 128 + tid];
    sci[tid] = g_cnt[ib*128 + tid];
    __syncthreads();

    unsigned myword = 0;
    unsigned tw[4];
    #pragma unroll 2
    for (int i0 = 0; i0 < 128; i0 += 2) {
        const unsigned* iwA = sib + i0 * AWORD;
        const unsigned* iwB = iwA + AWORD;
        int a0=0, a1=0, a2=0, a3=0, b0=0, b1=0, b2=0, b3=0;
        #pragma unroll
        for (int w = 0; w < 4; ++w) {
            a0 += __popc(jr[w]      & iwA[w]);
            a1 += __popc(jr[w + 4]  & iwA[w + 4]);
            a2 += __popc(jr[w + 8]  & iwA[w + 8]);
            a3 += __popc(jr[w + 12] & iwA[w + 12]);
            b0 += __popc(jr[w]      & iwB[w]);
            b1 += __popc(jr[w + 4]  & iwB[w + 4]);
            b2 += __popc(jr[w + 8]  & iwB[w + 8]);
            b3 += __popc(jr[w + 12] & iwB[w + 12]);
        }
        int iA = (a0 + a1) + (a2 + a3);
        int iB = (b0 + b1) + (b2 + b3);
        long long uA = (long long)(sj + sci[i0]     - iA);
        long long uB = (long long)(sj + sci[i0 + 1] - iB);
        bool posA = (iA > 0) && (((long long)iA << 26) >= 20132659LL * uA);
        bool posB = (iB > 0) && (((long long)iB << 26) >= 20132659LL * uB);
        myword |= (posA ? 1u : 0u) << (i0 & 31);
        myword |= (posB ? 1u : 0u) << ((i0 + 1) & 31);
        unsigned balA = __ballot_sync(0xffffffffu, posA);
        unsigned balB = __ballot_sync(0xffffffffu, posB);
        if ((i0 & 31) == lane)       tw[i0 >> 5] = balA;
        if (((i0 + 1) & 31) == lane) tw[i0 >> 5] = balB;
        if ((i0 & 31) == 30) {
            g_pm[(size_t)(jb*128 + tid) * 128 + ib*4 + (i0 >> 5)] = myword;
            myword = 0;
        }
    }
    if (ib != jb) {
        #pragma unroll
        for (int q = 0; q < 4; ++q)
            g_pm[(size_t)(ib*128 + q*32 + lane) * 128 + jb*4 + wid] = tw[q];
    }
}

// ---------------- kernel 3: persistent mma.sync tf32 GEMM + fused epilogue ----------------
// 512 threads, 16 warps in a 4x4 grid of 32x32 warp tiles.
// smem floats: As [0,16896), Bs0 [16896,33792), Bs1 [33792,50688), pm [50688,51712)
#define SM_A  0
#define SM_B0 16896
#define SM_B1 33792
#define SM_PM 50688
#define SMEM_FLOATS 51712

__device__ __forceinline__ void ld_tileA(uint32_t sb, int jb, int tid) {
    const float* Asrc = g_Z + (size_t)jb * 128 * D;
    #pragma unroll
    for (int it = 0; it < 8; ++it) {
        int idx = it * 512 + tid;
        int r = idx >> 5, k4 = idx & 31;
        cpa16(sb + (uint32_t)(r * PITCH + k4 * 4) * 4u, Asrc + r * 128 + k4 * 4);
    }
}
__device__ __forceinline__ void ld_tileB(uint32_t sb, int t, int jb, int tid) {
    const float* Bsrc = g_Z + (size_t)(t & 63) * 128 * D;
    uint32_t bo = sb + ((t & 1) ? SM_B1 : SM_B0) * 4u;
    #pragma unroll
    for (int it = 0; it < 8; ++it) {
        int idx = it * 512 + tid;
        int r = idx >> 5, k4 = idx & 31;
        cpa16(bo + (uint32_t)(r * PITCH + k4 * 4) * 4u, Bsrc + r * 128 + k4 * 4);
    }
    if (tid < 128)
        cpa16(sb + (SM_PM + (t & 1) * 512) * 4u + tid * 16,
              g_pm + (size_t)(jb * 128 + tid) * 128 + (((t & 63) & 31) << 2));
}

__global__ void __launch_bounds__(512, 1) kmain() {
    extern __shared__ float sm[];
    const int tid  = threadIdx.x;
    const int lane = tid & 31, wid = tid >> 5;
    const int wm   = wid >> 2, wn = wid & 3;      // 4 m-warps x 4 n-warps
    const int g    = lane >> 2, tg = lane & 3;

    const int t0 = blockIdx.x * CHUNK;
    const int t1 = min(t0 + CHUNK, 2048);
    if (t0 >= 2048) return;

    uint32_t sb = smem_u32(sm);

    float se[4] = {0,0,0,0}, ps[4] = {0,0,0,0}, np[4] = {0,0,0,0};
    int jb = t0 >> 6;

    ld_tileA(sb, jb, tid);
    ld_tileB(sb, t0, jb, tid);
    CP_COMMIT(); CP_WAIT0();
    __syncthreads();

    for (int t = t0; t < t1; ++t) {
        const int  ct   = t & 63;
        const bool same = (t + 1 < t1) && (((t + 1) >> 6) == jb);
        if (same) { ld_tileB(sb, t + 1, jb, tid); CP_COMMIT(); }

        const float*    Bs  = sm + ((t & 1) ? SM_B1 : SM_B0);
        const unsigned* pmS = (const unsigned*)(sm + SM_PM) + (t & 1) * 512;

        // ---- 32x32 warp tile: 2 m-frags x 4 n-frags, K=128 in 16 steps ----
        float d[2][4][4];
        #pragma unroll
        for (int mf = 0; mf < 2; ++mf)
            #pragma unroll
            for (int nf = 0; nf < 4; ++nf)
                #pragma unroll
                for (int q = 0; q < 4; ++q) d[mf][nf][q] = 0.0f;

        const float* Aw = sm + SM_A + (wm * 32) * PITCH;
        const float* Bw = Bs + (wn * 32) * PITCH;

        #pragma unroll 4
        for (int ks = 0; ks < 16; ++ks) {
            const int k0 = ks * 8;
            uint32_t a[2][4];
            #pragma unroll
            for (int mf = 0; mf < 2; ++mf) {
                const float* Ar = Aw + (mf * 16 + g) * PITCH + k0 + tg;
                a[mf][0] = __float_as_uint(Ar[0]);
                a[mf][1] = __float_as_uint(Ar[8 * PITCH]);
                a[mf][2] = __float_as_uint(Ar[4]);
                a[mf][3] = __float_as_uint(Ar[8 * PITCH + 4]);
            }
            #pragma unroll
            for (int nf = 0; nf < 4; ++nf) {
                const float* Br = Bw + (nf * 8 + g) * PITCH + k0 + tg;
                uint32_t b[2] = { __float_as_uint(Br[0]), __float_as_uint(Br[4]) };
                mma_tf32(d[0][nf], a[0], b);
                mma_tf32(d[1][nf], a[1], b);
            }
        }

        // ---- fused epilogue ----
        const int c0 = ct * 128;
        #pragma unroll
        for (int mf = 0; mf < 2; ++mf) {
            #pragma unroll
            for (int h = 0; h < 2; ++h) {
                const int rl   = wm * 32 + mf * 16 + h * 8 + g;
                const int jr   = jb * 128 + rl;
                const int jaug = jr + NROWS;
                const int ai   = mf * 2 + h;
                float a_se = 0.f, a_ps = 0.f, a_np = 0.f;
                #pragma unroll
                for (int nf = 0; nf < 4; ++nf) {
                    const int cl = wn * 32 + nf * 8 + tg * 2;
                    const unsigned w = pmS[rl * 4 + (cl >> 5)];
                    #pragma unroll
                    for (int q = 0; q < 2; ++q) {
                        const int cg = c0 + cl + q;
                        float v = d[mf][nf][h * 2 + q];
                        float s = fmaf(v, INV_TAU, -INV_TAU);
                        float e = __expf(s);
                        bool pos = (((w >> ((cl + q) & 31)) & 1u) != 0u) | (cg == jaug);
                        if (cg != jr) {
                            a_se += e;
                            if (pos) { a_ps += s; a_np += 1.f; }
                        }
                    }
                }
                se[ai] += a_se; ps[ai] += a_ps; np[ai] += a_np;
            }
        }

        if (same) CP_WAIT0();
        __syncthreads();

        if (!same) {
            // flush accumulators for this jb
            #pragma unroll
            for (int ai = 0; ai < 4; ++ai) {
                float a = se[ai], b = ps[ai], c = np[ai];
                a += __shfl_xor_sync(0xffffffffu, a, 1); a += __shfl_xor_sync(0xffffffffu, a, 2);
                b += __shfl_xor_sync(0xffffffffu, b, 1); b += __shfl_xor_sync(0xffffffffu, b, 2);
                c += __shfl_xor_sync(0xffffffffu, c, 1); c += __shfl_xor_sync(0xffffffffu, c, 2);
                if (tg == 0) {
                    int row = jb * 128 + wm * 32 + (ai >> 1) * 16 + (ai & 1) * 8 + g;
                    atomicAdd(&g_se[row], a);
                    atomicAdd(&g_ps[row], b);
                    atomicAdd(&g_np[row], c);
                }
                se[ai] = 0.f; ps[ai] = 0.f; np[ai] = 0.f;
            }
            if (t + 1 < t1) {
                jb = (t + 1) >> 6;
                ld_tileA(sb, jb, tid);
                ld_tileB(sb, t + 1, jb, tid);
                CP_COMMIT(); CP_WAIT0();
                __syncthreads();
            }
        }
    }
}

// ---------------- kernel 4: per-row loss + mean ----------------
__global__ void kfinal(float* __restrict__ out) {
    __shared__ float red[1024];
    int tid = threadIdx.x;
    float s = 0.0f;
    for (int i = tid; i < NROWS; i += 1024) {
        float npv = g_np[i];                 // >= 1 (aug column)
        s += -(g_ps[i] - npv * logf(g_se[i] + 1e-8f)) / npv;
    }
    red[tid] = s;
    __syncthreads();
    for (int o = 512; o; o >>= 1) {
        if (tid < o) red[tid] += red[tid + o];
        __syncthreads();
    }
    if (tid == 0) out[0] = red[0] / (float)NROWS;
}

// ---------------- launch ----------------
extern "C" void kernel_launch(void* const* d_in, const int* in_sizes, int n_in,
                              void* d_out, int out_size) {
    const float* z1     = (const float*)d_in[0];
    const float* z2     = (const float*)d_in[1];
    const int*   labels = (const int*)d_in[2];
    float* out = (float*)d_out;

    cudaFuncSetAttribute(kmain, cudaFuncAttributeMaxDynamicSharedMemorySize,
                         SMEM_FLOATS * 4);

    kprep<<<1536, 256>>>(z1, z2, labels);
    kjacc<<<528, 128>>>();
    kmain<<<NBLK, 512, SMEM_FLOATS * 4>>>();
    kfinal<<<1, 1024>>>(out);
}